// round 6
// baseline (speedup 1.0000x reference)
#include <cuda_runtime.h>

// EfConv: out[n, k*64+o] = b[o] + sum_{e: dst[e]==n} edge_feat[e,k] * z[src[e], o]
// where z = node_feat @ W^T.
//
// Pipeline:
//   0. zhist_kernel : z = nf @ W^T (64 nodes/block, 4x4 reg tile) + histogram
//   1. scan_kernel  : smem-resident scan producing 4-ALIGNED starts (padded)
//                     + real counts (g_cnt2); re-zeros g_counts
//   2. build_kernel : scatter (src<<8) + ef rows into aligned CSR order
//   3. gather_kernel: warp-per-node, zero smem: per 4-edge group one int4
//                     srcs broadcast + 4 MLP z loads; per edge 2 broadcast
//                     LDG.128 ef + 2 dup movs + 8 FFMA2. Padding slots are
//                     never written (stay 0) and tail ef loads are predicated.

#define MAX_N 50000
#define MAX_E 800000
#define MAX_P (MAX_E + 4 * MAX_N + 16)   // padded CSR capacity

__device__ float g_z[MAX_N * 64];
__device__ int   g_counts[MAX_N];
__device__ int   g_offsets[MAX_N + 1];   // 4-aligned starts
__device__ int   g_cnt2[MAX_N];          // real counts
__device__ int   g_cursor[MAX_N];
__device__ int   g_srcs[MAX_P];          // src<<8 (byte offset of z row); padding stays 0
__device__ float g_efs[(size_t)MAX_P * 8];

// ---------------------------------------------------------------------------
__global__ __launch_bounds__(256)
void zhist_kernel(const float* __restrict__ nf,
                  const float* __restrict__ W,
                  const int* __restrict__ dst, int N, int E) {
    __shared__ float Ws[64 * 68];
    __shared__ float nfs[64 * 64];
    int tid = threadIdx.x;

#pragma unroll
    for (int it = 0; it < 16; ++it) {
        int idx = it * 256 + tid;            // idx = o*64 + i
        int o = idx >> 6, i = idx & 63;
        Ws[i * 68 + o] = W[idx];
    }

    int nb = blockIdx.x * 64;
#pragma unroll
    for (int it = 0; it < 16; ++it) {
        int idx = it * 256 + tid;
        int n = nb + (idx >> 6);
        nfs[idx] = (n < N) ? nf[(size_t)n * 64 + (idx & 63)] : 0.0f;
    }

    int gs = gridDim.x * 256;
    int quads = (E + 3) >> 2;
    for (int u = blockIdx.x * 256 + tid; u < quads; u += gs) {
        int e4 = u * 4;
        if (e4 + 3 < E) {
            int4 d = *(const int4*)(dst + e4);
            atomicAdd(&g_counts[d.x], 1);
            atomicAdd(&g_counts[d.y], 1);
            atomicAdd(&g_counts[d.z], 1);
            atomicAdd(&g_counts[d.w], 1);
        } else {
            for (int e = e4; e < E; ++e) atomicAdd(&g_counts[dst[e]], 1);
        }
    }
    __syncthreads();

    int ng = tid >> 4;
    int ow = tid & 15;
    float acc[4][4];
#pragma unroll
    for (int j = 0; j < 4; ++j)
#pragma unroll
        for (int q = 0; q < 4; ++q) acc[j][q] = 0.0f;

#pragma unroll 4
    for (int i = 0; i < 64; ++i) {
        float4 wv = *(const float4*)(Ws + i * 68 + ow * 4);
        float a0 = nfs[(ng * 4 + 0) * 64 + i];
        float a1 = nfs[(ng * 4 + 1) * 64 + i];
        float a2 = nfs[(ng * 4 + 2) * 64 + i];
        float a3 = nfs[(ng * 4 + 3) * 64 + i];
        acc[0][0] += a0 * wv.x; acc[0][1] += a0 * wv.y; acc[0][2] += a0 * wv.z; acc[0][3] += a0 * wv.w;
        acc[1][0] += a1 * wv.x; acc[1][1] += a1 * wv.y; acc[1][2] += a1 * wv.z; acc[1][3] += a1 * wv.w;
        acc[2][0] += a2 * wv.x; acc[2][1] += a2 * wv.y; acc[2][2] += a2 * wv.z; acc[2][3] += a2 * wv.w;
        acc[3][0] += a3 * wv.x; acc[3][1] += a3 * wv.y; acc[3][2] += a3 * wv.z; acc[3][3] += a3 * wv.w;
    }

#pragma unroll
    for (int j = 0; j < 4; ++j) {
        int n = nb + ng * 4 + j;
        if (n < N)
            *(float4*)(g_z + (size_t)n * 64 + ow * 4) =
                make_float4(acc[j][0], acc[j][1], acc[j][2], acc[j][3]);
    }
}

// ---------------------------------------------------------------------------
// Smem-resident scan over PADDED counts (roundup-4) -> aligned starts.
// Also writes real counts to g_cnt2 and zeros g_counts for the next call.
// ---------------------------------------------------------------------------
__global__ __launch_bounds__(1024)
void scan_kernel(int N) {
    extern __shared__ int ss[];
    int* s    = ss;
    int* part = ss + N;
    int t = threadIdx.x;
    int C = (N + 1023) >> 10;

    for (int i = t; i < N; i += 1024) {
        s[i] = g_counts[i];
        g_counts[i] = 0;
    }
    __syncthreads();

    int base = t * C;
    int sum = 0;
    for (int i = 0; i < C; ++i) {
        int n = base + i;
        if (n < N) sum += (s[n] + 3) & ~3;
    }
    part[t] = sum;
    __syncthreads();

    for (int d = 1; d < 1024; d <<= 1) {
        int v = (t >= d) ? part[t - d] : 0;
        __syncthreads();
        part[t] += v;
        __syncthreads();
    }

    int run = (t == 0) ? 0 : part[t - 1];
    for (int i = 0; i < C; ++i) {
        int n = base + i;
        if (n < N) {
            int c = s[n];
            s[n] = run;                       // aligned start
            run += (c + 3) & ~3;
        }
    }
    __syncthreads();

    for (int i = t; i < N; i += 1024) {
        int v = s[i];
        g_offsets[i] = v;
        g_cursor[i]  = v;
        // real count: recompute not possible (s overwritten) -> reload below
    }
    __syncthreads();
    // write real counts (coalesced reload of original counts impossible now;
    // instead derive: cnt = next_aligned_start won't give it). So reload from
    // a second pass kept in part? Simplest: stash counts during first loop.
    // -- handled via g_cnt2 written in the first loop (see below). --
    if (t == 1023) g_offsets[N] = part[1023];
}

// NOTE: real counts are written by a tiny helper fused into the first loop of
// scan; to keep the kernel single-pass we instead write g_cnt2 there.
// (See modified first loop: we store counts to g_cnt2 before zeroing.)
// To keep code simple and correct, we do it in a dedicated pass below.
__global__ __launch_bounds__(1024)
void counts_save_kernel(int N) {
    int t = blockIdx.x * 1024 + threadIdx.x;
    if (t < N) g_cnt2[t] = g_counts[t];
}

// ---------------------------------------------------------------------------
__global__ __launch_bounds__(256)
void build_kernel(const int* __restrict__ dst,
                  const int* __restrict__ src,
                  const float* __restrict__ ef, int E) {
    int t = blockIdx.x * 256 + threadIdx.x;
    int e4 = t * 4;
    if (e4 + 3 < E) {
        int4 d = *(const int4*)(dst + e4);
        int4 s = *(const int4*)(src + e4);
        int p0 = atomicAdd(&g_cursor[d.x], 1);
        int p1 = atomicAdd(&g_cursor[d.y], 1);
        int p2 = atomicAdd(&g_cursor[d.z], 1);
        int p3 = atomicAdd(&g_cursor[d.w], 1);
        const float4* p = (const float4*)(ef + (size_t)e4 * 8);
        float4 a0 = p[0], b0 = p[1], a1 = p[2], b1 = p[3];
        float4 a2 = p[4], b2 = p[5], a3 = p[6], b3 = p[7];
        g_srcs[p0] = s.x << 8; g_srcs[p1] = s.y << 8;
        g_srcs[p2] = s.z << 8; g_srcs[p3] = s.w << 8;
        float4* q0 = (float4*)(g_efs + (size_t)p0 * 8); q0[0] = a0; q0[1] = b0;
        float4* q1 = (float4*)(g_efs + (size_t)p1 * 8); q1[0] = a1; q1[1] = b1;
        float4* q2 = (float4*)(g_efs + (size_t)p2 * 8); q2[0] = a2; q2[1] = b2;
        float4* q3 = (float4*)(g_efs + (size_t)p3 * 8); q3[0] = a3; q3[1] = b3;
    } else {
        for (int e = e4; e < E; ++e) {
            int pos = atomicAdd(&g_cursor[dst[e]], 1);
            g_srcs[pos] = src[e] << 8;
            const float4* p = (const float4*)(ef + (size_t)e * 8);
            float4 a = p[0], b = p[1];
            float4* q = (float4*)(g_efs + (size_t)pos * 8);
            q[0] = a; q[1] = b;
        }
    }
}

// ---------------------------------------------------------------------------
__device__ __forceinline__ void ffma2(unsigned long long& d,
                                      unsigned long long a,
                                      unsigned long long b) {
    asm("fma.rn.f32x2 %0, %1, %2, %0;" : "+l"(d) : "l"(a), "l"(b));
}
__device__ __forceinline__ unsigned long long dupf(float v) {
    unsigned long long r;
    asm("mov.b64 %0, {%1, %1};" : "=l"(r) : "r"(__float_as_uint(v)));
    return r;
}
__device__ __forceinline__ float2 unpack2(unsigned long long v) {
    unsigned int lo, hi;
    asm("mov.b64 {%0, %1}, %2;" : "=r"(lo), "=r"(hi) : "l"(v));
    return make_float2(__uint_as_float(lo), __uint_as_float(hi));
}

// ---------------------------------------------------------------------------
// Warp per node, no smem. acc[kp*2+c] = (out[2kp][2lane+c], out[2kp+1][2lane+c])
// packed f32x2 (bias-initialized). Per 4-edge group: 1 broadcast int4 srcs
// load (starts are 4-aligned), 4 independent z float2 loads; per edge:
// 2 broadcast LDG.128 ef pairs, 2 dup movs, 8 FFMA2. Tail group: ef loads
// predicated to zero; padding srcs are 0 (never written) -> z row 0, harmless.
// ---------------------------------------------------------------------------
__global__ __launch_bounds__(256)
void gather_kernel(const float* __restrict__ bias,
                   float* __restrict__ out, int N) {
    int w    = (blockIdx.x * blockDim.x + threadIdx.x) >> 5;
    int lane = threadIdx.x & 31;
    if (w >= N) return;

    int start = g_offsets[w];
    int cnt   = g_cnt2[w];

    float2 bv = ((const float2*)bias)[lane];
    unsigned long long acc[8];
#pragma unroll
    for (int kp = 0; kp < 4; ++kp) {
        acc[kp * 2 + 0] = dupf(bv.x);
        acc[kp * 2 + 1] = dupf(bv.y);
    }

    const char* zl = (const char*)g_z + lane * 8;
    int groups = (cnt + 3) >> 2;
    int rem = cnt & 3;

    for (int g = 0; g < groups; ++g) {
        int4 o4 = *(const int4*)(g_srcs + start + g * 4);
        float2 z0 = *(const float2*)(zl + o4.x);
        float2 z1 = *(const float2*)(zl + o4.y);
        float2 z2 = *(const float2*)(zl + o4.z);
        float2 z3 = *(const float2*)(zl + o4.w);

        bool full = (g + 1 < groups) || (rem == 0);
        int e0 = start + g * 4;

#pragma unroll
        for (int j = 0; j < 4; ++j) {
            float2 zj = (j == 0) ? z0 : (j == 1) ? z1 : (j == 2) ? z2 : z3;
            const ulonglong2* ep = (const ulonglong2*)(g_efs + (size_t)(e0 + j) * 8);
            ulonglong2 eA, eB;
            if (full || j < rem) {
                eA = ep[0];
                eB = ep[1];
            } else {
                eA = make_ulonglong2(0ull, 0ull);
                eB = make_ulonglong2(0ull, 0ull);
            }
            unsigned long long zx = dupf(zj.x);
            unsigned long long zy = dupf(zj.y);
            ffma2(acc[0], eA.x, zx);  ffma2(acc[1], eA.x, zy);
            ffma2(acc[2], eA.y, zx);  ffma2(acc[3], eA.y, zy);
            ffma2(acc[4], eB.x, zx);  ffma2(acc[5], eB.x, zy);
            ffma2(acc[6], eB.y, zx);  ffma2(acc[7], eB.y, zy);
        }
    }

    // epilogue: acc[kp*2+c] = (out[2kp][col_c], out[2kp+1][col_c]); repack to
    // row-major float2 stores at cols (2lane, 2lane+1).
    float* op = out + (size_t)w * 512 + 2 * lane;
#pragma unroll
    for (int kp = 0; kp < 4; ++kp) {
        float2 lo = unpack2(acc[kp * 2 + 0]);
        float2 hi = unpack2(acc[kp * 2 + 1]);
        *(float2*)(op + (2 * kp) * 64)     = make_float2(lo.x, hi.x);
        *(float2*)(op + (2 * kp + 1) * 64) = make_float2(lo.y, hi.y);
    }
}

// ---------------------------------------------------------------------------
extern "C" void kernel_launch(void* const* d_in, const int* in_sizes, int n_in,
                              void* d_out, int out_size) {
    const float* node_feat = (const float*)d_in[0];
    const float* edge_feat = (const float*)d_in[1];
    const float* W         = (const float*)d_in[2];
    const float* b         = (const float*)d_in[3];
    const int*   src       = (const int*)d_in[4];
    const int*   dst       = (const int*)d_in[5];
    float*       out       = (float*)d_out;

    int N = in_sizes[0] / 64;
    int E = in_sizes[4];

    size_t scan_smem = (size_t)(N + 1024) * sizeof(int);
    cudaFuncSetAttribute(scan_kernel,
                         cudaFuncAttributeMaxDynamicSharedMemorySize,
                         (int)scan_smem);

    int zb = (N + 63) / 64;
    zhist_kernel<<<zb, 256>>>(node_feat, W, dst, N, E);
    counts_save_kernel<<<(N + 1023) / 1024, 1024>>>(N);
    scan_kernel<<<1, 1024, scan_smem>>>(N);
    build_kernel<<<((E + 3) / 4 + 255) / 256, 256>>>(dst, src, edge_feat, E);
    gather_kernel<<<(N * 32 + 255) / 256, 256>>>(b, out, N);
}

// round 7
// speedup vs baseline: 1.3449x; 1.3449x over previous
#include <cuda_runtime.h>

// EfConv: out[n, k*64+o] = b[o] + sum_{e: dst[e]==n} edge_feat[e,k] * z[src[e], o]
// where z = node_feat @ W^T.
//
// Pipeline:
//   0. zhist_kernel : z = nf @ W^T (64 nodes/block, 4x4 reg tile) + histogram
//   1. scan_kernel  : smem-resident exclusive scan; re-zeros counts
//   2. build_kernel : scatter (src<<8) + ef rows into CSR order (8 edges/thr)
//   3. gather_kernel: warp-per-node; batch-resolve 32 edges into smem (raw ef
//                     pairs, conflict-free), inner loop: int4 offsets + 4 MLP
//                     z loads per group, 2 LDS.128 + 2 dup movs + 8 FFMA2
//                     per edge, branch-free (smem zero-padded).

#define MAX_N 50000
#define MAX_E 800000

__device__ float g_z[MAX_N * 64];
__device__ int   g_counts[MAX_N];
__device__ int   g_offsets[MAX_N + 1];
__device__ int   g_cursor[MAX_N];
__device__ int   g_srcs[MAX_E];          // src<<8 (byte offset of z row)
__device__ float g_efs[(size_t)MAX_E * 8];

// ---------------------------------------------------------------------------
__global__ __launch_bounds__(256)
void zhist_kernel(const float* __restrict__ nf,
                  const float* __restrict__ W,
                  const int* __restrict__ dst, int N, int E) {
    __shared__ float Ws[64 * 68];
    __shared__ float nfs[64 * 64];
    int tid = threadIdx.x;

#pragma unroll
    for (int it = 0; it < 16; ++it) {
        int idx = it * 256 + tid;            // idx = o*64 + i
        int o = idx >> 6, i = idx & 63;
        Ws[i * 68 + o] = W[idx];
    }

    int nb = blockIdx.x * 64;
#pragma unroll
    for (int it = 0; it < 16; ++it) {
        int idx = it * 256 + tid;
        int n = nb + (idx >> 6);
        nfs[idx] = (n < N) ? nf[(size_t)n * 64 + (idx & 63)] : 0.0f;
    }

    int gs = gridDim.x * 256;
    int quads = (E + 3) >> 2;
    for (int u = blockIdx.x * 256 + tid; u < quads; u += gs) {
        int e4 = u * 4;
        if (e4 + 3 < E) {
            int4 d = *(const int4*)(dst + e4);
            atomicAdd(&g_counts[d.x], 1);
            atomicAdd(&g_counts[d.y], 1);
            atomicAdd(&g_counts[d.z], 1);
            atomicAdd(&g_counts[d.w], 1);
        } else {
            for (int e = e4; e < E; ++e) atomicAdd(&g_counts[dst[e]], 1);
        }
    }
    __syncthreads();

    int ng = tid >> 4;
    int ow = tid & 15;
    float acc[4][4];
#pragma unroll
    for (int j = 0; j < 4; ++j)
#pragma unroll
        for (int q = 0; q < 4; ++q) acc[j][q] = 0.0f;

#pragma unroll 4
    for (int i = 0; i < 64; ++i) {
        float4 wv = *(const float4*)(Ws + i * 68 + ow * 4);
        float a0 = nfs[(ng * 4 + 0) * 64 + i];
        float a1 = nfs[(ng * 4 + 1) * 64 + i];
        float a2 = nfs[(ng * 4 + 2) * 64 + i];
        float a3 = nfs[(ng * 4 + 3) * 64 + i];
        acc[0][0] += a0 * wv.x; acc[0][1] += a0 * wv.y; acc[0][2] += a0 * wv.z; acc[0][3] += a0 * wv.w;
        acc[1][0] += a1 * wv.x; acc[1][1] += a1 * wv.y; acc[1][2] += a1 * wv.z; acc[1][3] += a1 * wv.w;
        acc[2][0] += a2 * wv.x; acc[2][1] += a2 * wv.y; acc[2][2] += a2 * wv.z; acc[2][3] += a2 * wv.w;
        acc[3][0] += a3 * wv.x; acc[3][1] += a3 * wv.y; acc[3][2] += a3 * wv.z; acc[3][3] += a3 * wv.w;
    }

#pragma unroll
    for (int j = 0; j < 4; ++j) {
        int n = nb + ng * 4 + j;
        if (n < N)
            *(float4*)(g_z + (size_t)n * 64 + ow * 4) =
                make_float4(acc[j][0], acc[j][1], acc[j][2], acc[j][3]);
    }
}

// ---------------------------------------------------------------------------
__global__ __launch_bounds__(1024)
void scan_kernel(int N) {
    extern __shared__ int ss[];
    int* s    = ss;
    int* part = ss + N;
    int t = threadIdx.x;
    int C = (N + 1023) >> 10;

    for (int i = t; i < N; i += 1024) {
        s[i] = g_counts[i];
        g_counts[i] = 0;
    }
    __syncthreads();

    int base = t * C;
    int sum = 0;
    for (int i = 0; i < C; ++i) {
        int n = base + i;
        if (n < N) sum += s[n];
    }
    part[t] = sum;
    __syncthreads();

    for (int d = 1; d < 1024; d <<= 1) {
        int v = (t >= d) ? part[t - d] : 0;
        __syncthreads();
        part[t] += v;
        __syncthreads();
    }

    int run = (t == 0) ? 0 : part[t - 1];
    for (int i = 0; i < C; ++i) {
        int n = base + i;
        if (n < N) {
            int c = s[n];
            s[n] = run;
            run += c;
        }
    }
    __syncthreads();

    for (int i = t; i < N; i += 1024) {
        int v = s[i];
        g_offsets[i] = v;
        g_cursor[i]  = v;
    }
    if (t == 1023) g_offsets[N] = part[1023];
}

// ---------------------------------------------------------------------------
// Scatter src + ef rows into dst-sorted order. 8 edges/thread for MLP on the
// 318-cyc ATOMG chain.
// ---------------------------------------------------------------------------
__global__ __launch_bounds__(256)
void build_kernel(const int* __restrict__ dst,
                  const int* __restrict__ src,
                  const float* __restrict__ ef, int E) {
    int t = blockIdx.x * 256 + threadIdx.x;
    int e8 = t * 8;
    if (e8 + 7 < E) {
        int4 d0 = *(const int4*)(dst + e8);
        int4 d1 = *(const int4*)(dst + e8 + 4);
        int4 s0 = *(const int4*)(src + e8);
        int4 s1 = *(const int4*)(src + e8 + 4);
        int p0 = atomicAdd(&g_cursor[d0.x], 1);
        int p1 = atomicAdd(&g_cursor[d0.y], 1);
        int p2 = atomicAdd(&g_cursor[d0.z], 1);
        int p3 = atomicAdd(&g_cursor[d0.w], 1);
        int p4 = atomicAdd(&g_cursor[d1.x], 1);
        int p5 = atomicAdd(&g_cursor[d1.y], 1);
        int p6 = atomicAdd(&g_cursor[d1.z], 1);
        int p7 = atomicAdd(&g_cursor[d1.w], 1);
        const float4* p = (const float4*)(ef + (size_t)e8 * 8);
        g_srcs[p0] = s0.x << 8; g_srcs[p1] = s0.y << 8;
        g_srcs[p2] = s0.z << 8; g_srcs[p3] = s0.w << 8;
        g_srcs[p4] = s1.x << 8; g_srcs[p5] = s1.y << 8;
        g_srcs[p6] = s1.z << 8; g_srcs[p7] = s1.w << 8;
        int pos[8] = {p0, p1, p2, p3, p4, p5, p6, p7};
#pragma unroll
        for (int j = 0; j < 8; ++j) {
            float4 a = p[j * 2];
            float4 b = p[j * 2 + 1];
            float4* q = (float4*)(g_efs + (size_t)pos[j] * 8);
            q[0] = a;
            q[1] = b;
        }
    } else {
        for (int e = e8; e < E; ++e) {
            int pp = atomicAdd(&g_cursor[dst[e]], 1);
            g_srcs[pp] = src[e] << 8;
            const float4* p = (const float4*)(ef + (size_t)e * 8);
            float4 a = p[0], b = p[1];
            float4* q = (float4*)(g_efs + (size_t)pp * 8);
            q[0] = a; q[1] = b;
        }
    }
}

// ---------------------------------------------------------------------------
__device__ __forceinline__ void ffma2(unsigned long long& d,
                                      unsigned long long a,
                                      unsigned long long b) {
    asm("fma.rn.f32x2 %0, %1, %2, %0;" : "+l"(d) : "l"(a), "l"(b));
}
__device__ __forceinline__ unsigned long long dupf(float v) {
    unsigned long long r;
    asm("mov.b64 %0, {%1, %1};" : "=l"(r) : "r"(__float_as_uint(v)));
    return r;
}
__device__ __forceinline__ float2 unpack2(unsigned long long v) {
    unsigned int lo, hi;
    asm("mov.b64 {%0, %1}, %2;" : "=r"(lo), "=r"(hi) : "l"(v));
    return make_float2(__uint_as_float(lo), __uint_as_float(hi));
}

// ---------------------------------------------------------------------------
// Warp per node. acc[kp] = (out[2kp][c0], out[2kp+1][c0]) packed f32x2,
// acc[4+kp] same for c1, where (c0,c1) = (2*lane, 2*lane+1).
// Per 32-edge batch: lane-parallel resolve of offsets + raw ef pairs into
// conflict-free smem (zero-padded for lanes >= m). Inner loop: per 4-edge
// group one int4 offset LDS + 4 independent z float2 loads; per edge two
// broadcast LDS.128 + 2 dup movs + 8 FFMA2. Branch-free.
// ---------------------------------------------------------------------------
__global__ __launch_bounds__(256)
void gather_kernel(const float* __restrict__ bias,
                   float* __restrict__ out, int N) {
    __shared__ __align__(16) float4 sA[8][32];
    __shared__ __align__(16) float4 sB[8][32];
    __shared__ int sOf[8][32];
    int wblk = threadIdx.x >> 5;
    int w    = (blockIdx.x * blockDim.x + threadIdx.x) >> 5;
    int lane = threadIdx.x & 31;
    if (w >= N) return;

    int start = g_offsets[w];
    int cnt   = g_offsets[w + 1] - start;

    float2 bv = ((const float2*)bias)[lane];
    unsigned long long acc[8];
#pragma unroll
    for (int kp = 0; kp < 4; ++kp) {
        acc[kp]     = dupf(bv.x);
        acc[4 + kp] = dupf(bv.y);
    }

    const char* zl = (const char*)g_z + lane * 8;

    for (int base = 0; base < cnt; base += 32) {
        int m = min(32, cnt - base);
        int idx = start + base + lane;
        int off = 0;
        float4 ea = make_float4(0.f, 0.f, 0.f, 0.f);
        float4 eb = make_float4(0.f, 0.f, 0.f, 0.f);
        if (lane < m) {
            off = g_srcs[idx];
            const float4* p = (const float4*)(g_efs + (size_t)idx * 8);
            ea = p[0];
            eb = p[1];
        }
        sOf[wblk][lane] = off;
        sA[wblk][lane] = ea;
        sB[wblk][lane] = eb;
        __syncwarp();

        int groups = (m + 3) >> 2;
        for (int g = 0; g < groups; ++g) {
            int4 o4 = *(const int4*)&sOf[wblk][g * 4];
            float2 z0 = *(const float2*)(zl + o4.x);
            float2 z1 = *(const float2*)(zl + o4.y);
            float2 z2 = *(const float2*)(zl + o4.z);
            float2 z3 = *(const float2*)(zl + o4.w);

#pragma unroll
            for (int j = 0; j < 4; ++j) {
                float2 zj = (j == 0) ? z0 : (j == 1) ? z1 : (j == 2) ? z2 : z3;
                int e = g * 4 + j;
                ulonglong2 eA = *(const ulonglong2*)&sA[wblk][e];
                ulonglong2 eB = *(const ulonglong2*)&sB[wblk][e];
                unsigned long long zx = dupf(zj.x);
                unsigned long long zy = dupf(zj.y);
                ffma2(acc[0], eA.x, zx);  ffma2(acc[4], eA.x, zy);
                ffma2(acc[1], eA.y, zx);  ffma2(acc[5], eA.y, zy);
                ffma2(acc[2], eB.x, zx);  ffma2(acc[6], eB.x, zy);
                ffma2(acc[3], eB.y, zx);  ffma2(acc[7], eB.y, zy);
            }
        }
        __syncwarp();
    }

    float* op = out + (size_t)w * 512 + 2 * lane;
#pragma unroll
    for (int kp = 0; kp < 4; ++kp) {
        float2 lo = unpack2(acc[kp]);       // (out[2kp][c0], out[2kp+1][c0])
        float2 hi = unpack2(acc[4 + kp]);   // (out[2kp][c1], out[2kp+1][c1])
        *(float2*)(op + (2 * kp) * 64)     = make_float2(lo.x, hi.x);
        *(float2*)(op + (2 * kp + 1) * 64) = make_float2(lo.y, hi.y);
    }
}

// ---------------------------------------------------------------------------
extern "C" void kernel_launch(void* const* d_in, const int* in_sizes, int n_in,
                              void* d_out, int out_size) {
    const float* node_feat = (const float*)d_in[0];
    const float* edge_feat = (const float*)d_in[1];
    const float* W         = (const float*)d_in[2];
    const float* b         = (const float*)d_in[3];
    const int*   src       = (const int*)d_in[4];
    const int*   dst       = (const int*)d_in[5];
    float*       out       = (float*)d_out;

    int N = in_sizes[0] / 64;
    int E = in_sizes[4];

    size_t scan_smem = (size_t)(N + 1024) * sizeof(int);
    cudaFuncSetAttribute(scan_kernel,
                         cudaFuncAttributeMaxDynamicSharedMemorySize,
                         (int)scan_smem);

    int zb = (N + 63) / 64;
    zhist_kernel<<<zb, 256>>>(node_feat, W, dst, N, E);
    scan_kernel<<<1, 1024, scan_smem>>>(N);
    build_kernel<<<((E + 7) / 8 + 255) / 256, 256>>>(dst, src, edge_feat, E);
    gather_kernel<<<(N * 32 + 255) / 256, 256>>>(b, out, N);
}

// round 8
// speedup vs baseline: 1.3859x; 1.0305x over previous
#include <cuda_runtime.h>

// EfConv: out[n, k*64+o] = b[o] + sum_{e: dst[e]==n} edge_feat[e,k] * z[src[e], o]
// where z = node_feat @ W^T.
//
// Pipeline:
//   0. zhist_kernel : z = nf @ W^T (64 nodes/block, 4x4 reg tile) + histogram
//   1. scan_kernel  : smem-resident scan (warp-shuffle hierarchy); re-zeros counts
//   2. build_kernel : scatter (src<<8) + ef rows into CSR order (8 edges/thr)
//   3. gather_kernel: warp-per-node; batch-resolve 32 edges into smem, inner
//                     loop SOFTWARE-PIPELINED across 4-edge groups (next
//                     group's offsets+z issued before current group's FMAs).

#define MAX_N 50000
#define MAX_E 800000

__device__ float g_z[MAX_N * 64];
__device__ int   g_counts[MAX_N];
__device__ int   g_offsets[MAX_N + 1];
__device__ int   g_cursor[MAX_N];
__device__ int   g_srcs[MAX_E];          // src<<8 (byte offset of z row)
__device__ float g_efs[(size_t)MAX_E * 8];

// ---------------------------------------------------------------------------
__global__ __launch_bounds__(256)
void zhist_kernel(const float* __restrict__ nf,
                  const float* __restrict__ W,
                  const int* __restrict__ dst, int N, int E) {
    __shared__ float Ws[64 * 68];
    __shared__ float nfs[64 * 64];
    int tid = threadIdx.x;

#pragma unroll
    for (int it = 0; it < 16; ++it) {
        int idx = it * 256 + tid;            // idx = o*64 + i
        int o = idx >> 6, i = idx & 63;
        Ws[i * 68 + o] = W[idx];
    }

    int nb = blockIdx.x * 64;
#pragma unroll
    for (int it = 0; it < 16; ++it) {
        int idx = it * 256 + tid;
        int n = nb + (idx >> 6);
        nfs[idx] = (n < N) ? nf[(size_t)n * 64 + (idx & 63)] : 0.0f;
    }

    int gs = gridDim.x * 256;
    int quads = (E + 3) >> 2;
    for (int u = blockIdx.x * 256 + tid; u < quads; u += gs) {
        int e4 = u * 4;
        if (e4 + 3 < E) {
            int4 d = *(const int4*)(dst + e4);
            atomicAdd(&g_counts[d.x], 1);
            atomicAdd(&g_counts[d.y], 1);
            atomicAdd(&g_counts[d.z], 1);
            atomicAdd(&g_counts[d.w], 1);
        } else {
            for (int e = e4; e < E; ++e) atomicAdd(&g_counts[dst[e]], 1);
        }
    }
    __syncthreads();

    int ng = tid >> 4;
    int ow = tid & 15;
    float acc[4][4];
#pragma unroll
    for (int j = 0; j < 4; ++j)
#pragma unroll
        for (int q = 0; q < 4; ++q) acc[j][q] = 0.0f;

#pragma unroll 4
    for (int i = 0; i < 64; ++i) {
        float4 wv = *(const float4*)(Ws + i * 68 + ow * 4);
        float a0 = nfs[(ng * 4 + 0) * 64 + i];
        float a1 = nfs[(ng * 4 + 1) * 64 + i];
        float a2 = nfs[(ng * 4 + 2) * 64 + i];
        float a3 = nfs[(ng * 4 + 3) * 64 + i];
        acc[0][0] += a0 * wv.x; acc[0][1] += a0 * wv.y; acc[0][2] += a0 * wv.z; acc[0][3] += a0 * wv.w;
        acc[1][0] += a1 * wv.x; acc[1][1] += a1 * wv.y; acc[1][2] += a1 * wv.z; acc[1][3] += a1 * wv.w;
        acc[2][0] += a2 * wv.x; acc[2][1] += a2 * wv.y; acc[2][2] += a2 * wv.z; acc[2][3] += a2 * wv.w;
        acc[3][0] += a3 * wv.x; acc[3][1] += a3 * wv.y; acc[3][2] += a3 * wv.z; acc[3][3] += a3 * wv.w;
    }

#pragma unroll
    for (int j = 0; j < 4; ++j) {
        int n = nb + ng * 4 + j;
        if (n < N)
            *(float4*)(g_z + (size_t)n * 64 + ow * 4) =
                make_float4(acc[j][0], acc[j][1], acc[j][2], acc[j][3]);
    }
}

// ---------------------------------------------------------------------------
// Smem-resident exclusive scan, warp-shuffle hierarchy (2 barriers total).
// ---------------------------------------------------------------------------
__global__ __launch_bounds__(1024)
void scan_kernel(int N) {
    extern __shared__ int ss[];
    int* s     = ss;          // [N]
    int* wsum  = ss + N;      // [32] warp partial sums
    int t    = threadIdx.x;
    int lane = t & 31;
    int wid  = t >> 5;
    int C = (N + 1023) >> 10;

    for (int i = t; i < N; i += 1024) {
        s[i] = g_counts[i];
        g_counts[i] = 0;
    }
    __syncthreads();

    int base = t * C;
    int sum = 0;
    for (int i = 0; i < C; ++i) {
        int n = base + i;
        if (n < N) sum += s[n];
    }

    // inclusive shfl-scan within warp
    int v = sum;
#pragma unroll
    for (int d = 1; d < 32; d <<= 1) {
        int u = __shfl_up_sync(0xffffffffu, v, d);
        if (lane >= d) v += u;
    }
    if (lane == 31) wsum[wid] = v;
    __syncthreads();

    if (wid == 0) {
        int wv = wsum[lane];
#pragma unroll
        for (int d = 1; d < 32; d <<= 1) {
            int u = __shfl_up_sync(0xffffffffu, wv, d);
            if (lane >= d) wv += u;
        }
        wsum[lane] = wv;
    }
    __syncthreads();

    int excl = v - sum + (wid > 0 ? wsum[wid - 1] : 0);  // exclusive prefix of thread chunks
    int total = wsum[31];

    int run = excl;
    for (int i = 0; i < C; ++i) {
        int n = base + i;
        if (n < N) {
            int c = s[n];
            s[n] = run;
            run += c;
        }
    }
    __syncthreads();

    for (int i = t; i < N; i += 1024) {
        int o = s[i];
        g_offsets[i] = o;
        g_cursor[i]  = o;
    }
    if (t == 0) g_offsets[N] = total;
}

// ---------------------------------------------------------------------------
__global__ __launch_bounds__(256)
void build_kernel(const int* __restrict__ dst,
                  const int* __restrict__ src,
                  const float* __restrict__ ef, int E) {
    int t = blockIdx.x * 256 + threadIdx.x;
    int e8 = t * 8;
    if (e8 + 7 < E) {
        int4 d0 = *(const int4*)(dst + e8);
        int4 d1 = *(const int4*)(dst + e8 + 4);
        int4 s0 = *(const int4*)(src + e8);
        int4 s1 = *(const int4*)(src + e8 + 4);
        int p0 = atomicAdd(&g_cursor[d0.x], 1);
        int p1 = atomicAdd(&g_cursor[d0.y], 1);
        int p2 = atomicAdd(&g_cursor[d0.z], 1);
        int p3 = atomicAdd(&g_cursor[d0.w], 1);
        int p4 = atomicAdd(&g_cursor[d1.x], 1);
        int p5 = atomicAdd(&g_cursor[d1.y], 1);
        int p6 = atomicAdd(&g_cursor[d1.z], 1);
        int p7 = atomicAdd(&g_cursor[d1.w], 1);
        const float4* p = (const float4*)(ef + (size_t)e8 * 8);
        g_srcs[p0] = s0.x << 8; g_srcs[p1] = s0.y << 8;
        g_srcs[p2] = s0.z << 8; g_srcs[p3] = s0.w << 8;
        g_srcs[p4] = s1.x << 8; g_srcs[p5] = s1.y << 8;
        g_srcs[p6] = s1.z << 8; g_srcs[p7] = s1.w << 8;
        int pos[8] = {p0, p1, p2, p3, p4, p5, p6, p7};
#pragma unroll
        for (int j = 0; j < 8; ++j) {
            float4 a = p[j * 2];
            float4 b = p[j * 2 + 1];
            float4* q = (float4*)(g_efs + (size_t)pos[j] * 8);
            q[0] = a;
            q[1] = b;
        }
    } else {
        for (int e = e8; e < E; ++e) {
            int pp = atomicAdd(&g_cursor[dst[e]], 1);
            g_srcs[pp] = src[e] << 8;
            const float4* p = (const float4*)(ef + (size_t)e * 8);
            float4 a = p[0], b = p[1];
            float4* q = (float4*)(g_efs + (size_t)pp * 8);
            q[0] = a; q[1] = b;
        }
    }
}

// ---------------------------------------------------------------------------
__device__ __forceinline__ void ffma2(unsigned long long& d,
                                      unsigned long long a,
                                      unsigned long long b) {
    asm("fma.rn.f32x2 %0, %1, %2, %0;" : "+l"(d) : "l"(a), "l"(b));
}
__device__ __forceinline__ unsigned long long dupf(float v) {
    unsigned long long r;
    asm("mov.b64 %0, {%1, %1};" : "=l"(r) : "r"(__float_as_uint(v)));
    return r;
}
__device__ __forceinline__ float2 unpack2(unsigned long long v) {
    unsigned int lo, hi;
    asm("mov.b64 {%0, %1}, %2;" : "=r"(lo), "=r"(hi) : "l"(v));
    return make_float2(__uint_as_float(lo), __uint_as_float(hi));
}

// ---------------------------------------------------------------------------
// Warp per node, software-pipelined inner loop.
// acc[kp] = (out[2kp][c0], out[2kp+1][c0]), acc[4+kp] same for c1,
// (c0,c1) = (2*lane, 2*lane+1).
// Per 32-edge batch: lane-parallel resolve into conflict-free smem (zero-
// padded). Inner loop over 4-edge groups: issue group g+1's int4 offsets and
// 4 z loads (clamped index -> branch-free; redundant last load is an L1 hit),
// then do group g's 32 FFMA2.
// ---------------------------------------------------------------------------
__global__ __launch_bounds__(256)
void gather_kernel(const float* __restrict__ bias,
                   float* __restrict__ out, int N) {
    __shared__ __align__(16) float4 sA[8][32];
    __shared__ __align__(16) float4 sB[8][32];
    __shared__ __align__(16) int sOf[8][32];
    int wblk = threadIdx.x >> 5;
    int w    = (blockIdx.x * blockDim.x + threadIdx.x) >> 5;
    int lane = threadIdx.x & 31;
    if (w >= N) return;

    int start = g_offsets[w];
    int cnt   = g_offsets[w + 1] - start;

    float2 bv = ((const float2*)bias)[lane];
    unsigned long long acc[8];
#pragma unroll
    for (int kp = 0; kp < 4; ++kp) {
        acc[kp]     = dupf(bv.x);
        acc[4 + kp] = dupf(bv.y);
    }

    const char* zl = (const char*)g_z + lane * 8;

    for (int base = 0; base < cnt; base += 32) {
        int m = min(32, cnt - base);
        int idx = start + base + lane;
        int off = 0;
        float4 ea = make_float4(0.f, 0.f, 0.f, 0.f);
        float4 eb = make_float4(0.f, 0.f, 0.f, 0.f);
        if (lane < m) {
            off = g_srcs[idx];
            const float4* p = (const float4*)(g_efs + (size_t)idx * 8);
            ea = p[0];
            eb = p[1];
        }
        sOf[wblk][lane] = off;
        sA[wblk][lane] = ea;
        sB[wblk][lane] = eb;
        __syncwarp();

        int groups = (m + 3) >> 2;
        int last = groups - 1;

        // prologue: group 0 z loads
        int4 o4 = *(const int4*)&sOf[wblk][0];
        float2 z0 = *(const float2*)(zl + o4.x);
        float2 z1 = *(const float2*)(zl + o4.y);
        float2 z2 = *(const float2*)(zl + o4.z);
        float2 z3 = *(const float2*)(zl + o4.w);

        for (int g = 0; g < groups; ++g) {
            // issue next group's loads (clamped -> branch-free)
            int gn = (g < last) ? g + 1 : last;
            int4 o4n = *(const int4*)&sOf[wblk][gn * 4];
            float2 y0 = *(const float2*)(zl + o4n.x);
            float2 y1 = *(const float2*)(zl + o4n.y);
            float2 y2 = *(const float2*)(zl + o4n.z);
            float2 y3 = *(const float2*)(zl + o4n.w);

#pragma unroll
            for (int j = 0; j < 4; ++j) {
                float2 zj = (j == 0) ? z0 : (j == 1) ? z1 : (j == 2) ? z2 : z3;
                int e = g * 4 + j;
                ulonglong2 eA = *(const ulonglong2*)&sA[wblk][e];
                ulonglong2 eB = *(const ulonglong2*)&sB[wblk][e];
                unsigned long long zx = dupf(zj.x);
                unsigned long long zy = dupf(zj.y);
                ffma2(acc[0], eA.x, zx);  ffma2(acc[4], eA.x, zy);
                ffma2(acc[1], eA.y, zx);  ffma2(acc[5], eA.y, zy);
                ffma2(acc[2], eB.x, zx);  ffma2(acc[6], eB.x, zy);
                ffma2(acc[3], eB.y, zx);  ffma2(acc[7], eB.y, zy);
            }
            z0 = y0; z1 = y1; z2 = y2; z3 = y3;
        }
        __syncwarp();
    }

    float* op = out + (size_t)w * 512 + 2 * lane;
#pragma unroll
    for (int kp = 0; kp < 4; ++kp) {
        float2 lo = unpack2(acc[kp]);
        float2 hi = unpack2(acc[4 + kp]);
        *(float2*)(op + (2 * kp) * 64)     = make_float2(lo.x, hi.x);
        *(float2*)(op + (2 * kp + 1) * 64) = make_float2(lo.y, hi.y);
    }
}

// ---------------------------------------------------------------------------
extern "C" void kernel_launch(void* const* d_in, const int* in_sizes, int n_in,
                              void* d_out, int out_size) {
    const float* node_feat = (const float*)d_in[0];
    const float* edge_feat = (const float*)d_in[1];
    const float* W         = (const float*)d_in[2];
    const float* b         = (const float*)d_in[3];
    const int*   src       = (const int*)d_in[4];
    const int*   dst       = (const int*)d_in[5];
    float*       out       = (float*)d_out;

    int N = in_sizes[0] / 64;
    int E = in_sizes[4];

    size_t scan_smem = (size_t)(N + 32) * sizeof(int);
    cudaFuncSetAttribute(scan_kernel,
                         cudaFuncAttributeMaxDynamicSharedMemorySize,
                         (int)scan_smem);

    int zb = (N + 63) / 64;
    zhist_kernel<<<zb, 256>>>(node_feat, W, dst, N, E);
    scan_kernel<<<1, 1024, scan_smem>>>(N);
    build_kernel<<<((E + 7) / 8 + 255) / 256, 256>>>(dst, src, edge_feat, E);
    gather_kernel<<<(N * 32 + 255) / 256, 256>>>(b, out, N);
}